// round 13
// baseline (speedup 1.0000x reference)
#include <cuda_runtime.h>

#define BATCH   8
#define NPTS    4096
#define NP      1024
#define NS      32
#define MROWS   262144
#define NQ      8192
#define NSRC    32768
#define RAD2    0.04f

typedef unsigned long long ull;
typedef unsigned int uint;

// ---------------- device scratch ----------------
__device__ float  g_F[NSRC*64];
__device__ float  g_Y1[(size_t)MROWS*64];
__device__ float  g_max[NQ*128];
__device__ float  g_nxyz[NQ*3];
__device__ int    g_gi[MROWS];
__device__ float2 g_p0[2048*64];
__device__ float2 g_p1[1024*64];
__device__ float2 g_p2[2048*128];
__device__ float  g_sc0[64], g_sh0[64];
__device__ float  g_sc1[64], g_sh1[64];
__device__ float  g_sc2[128], g_sh2[128];
__device__ float  g_sx[NSRC], g_sy[NSRC], g_sz[NSRC];
__device__ float  g_W1d[64*128];
__device__ float  g_W2d[64*256];
__device__ uint   g_prog[8];
__device__ uint   g_ctr[3];

// ---------------- helpers ----------------
__device__ __forceinline__ void fma2(ull& d, ull a, ull b) {
    asm("fma.rn.f32x2 %0, %1, %2, %0;" : "+l"(d) : "l"(a), "l"(b));
}
__device__ __forceinline__ ull mul2(ull a, ull b) {
    ull d; asm("mul.rn.f32x2 %0, %1, %2;" : "=l"(d) : "l"(a), "l"(b)); return d;
}
__device__ __forceinline__ ull add2(ull a, ull b) {
    ull d; asm("add.rn.f32x2 %0, %1, %2;" : "=l"(d) : "l"(a), "l"(b)); return d;
}
__device__ __forceinline__ ull pack2(float lo, float hi) {
    ull d; asm("mov.b64 %0, {%1, %2};" : "=l"(d) : "f"(lo), "f"(hi)); return d;
}
__device__ __forceinline__ float2 u2f2(ull v) {
    float2 r; asm("mov.b64 {%0, %1}, %2;" : "=f"(r.x), "=f"(r.y) : "l"(v)); return r;
}
__device__ __forceinline__ uint rmax(uint v) {
    uint r; asm("redux.sync.max.u32 %0, %1, 0xffffffff;" : "=r"(r) : "r"(v)); return r;
}
__device__ __forceinline__ uint rmin(uint v) {
    uint r; asm("redux.sync.min.u32 %0, %1, 0xffffffff;" : "=r"(r) : "r"(v)); return r;
}
__device__ __forceinline__ uint ld_acq(const uint* p) {
    uint v; asm volatile("ld.acquire.gpu.u32 %0, [%1];" : "=r"(v) : "l"(p)); return v;
}
__device__ __forceinline__ void st_rel(uint* p, uint v) {
    asm volatile("st.release.gpu.u32 [%0], %1;" :: "l"(p), "r"(v) : "memory");
}

// ---------------- in-kernel BN finalize (last-block pattern) ----------------
template<int C, int NB, int TPB>
__device__ void finalize_inblock(const float2* __restrict__ part,
                                 const float* __restrict__ gam,
                                 const float* __restrict__ bet,
                                 float* __restrict__ sc, float* __restrict__ sh,
                                 double* ws)   // 2*TPB doubles
{
    constexpr int PERC = TPB / C;
    double* fsd = ws;
    double* fsq = ws + TPB;
    const int tid = threadIdx.x;
    const int c = tid % C, rg = tid / C;
    double s = 0.0, q = 0.0;
    for (int i = rg; i < NB; i += PERC) {
        const float2 v = part[i*C + c];
        s += (double)v.x; q += (double)v.y;
    }
    fsd[tid] = s; fsq[tid] = q;
    __syncthreads();
    if (tid < C) {
        double ts = 0.0, tq = 0.0;
#pragma unroll
        for (int g = 0; g < PERC; ++g) { ts += fsd[g*C + tid]; tq += fsq[g*C + tid]; }
        const double mu  = ts / (double)MROWS;
        const double var = tq / (double)MROWS - mu*mu;
        const float rs = (float)rsqrt(var + 1e-5);
        const float scv = gam[tid] * rs;
        sc[tid] = scv;
        sh[tid] = bet[tid] - (float)mu * scv;
    }
}

// ======================= prep: SoA + weight permutation + resets =======================
__global__ __launch_bounds__(256) void prep_kernel(const float* __restrict__ xyz,
                                                   const float* __restrict__ w1,
                                                   const float* __restrict__ w2)
{
    const int tid = threadIdx.x, bx = blockIdx.x;
    if (bx < 128) {
        const int i = bx*256 + tid;
        const float x = xyz[i*3+0], y = xyz[i*3+1], z = xyz[i*3+2];
        g_sx[i] = x; g_sy[i] = y; g_sz[i] = z;
        if (bx == 0 && tid < 11) {
            if (tid < 8) g_prog[tid] = 0;
            else         g_ctr[tid-8] = 0;
        }
    } else if (bx < 144) {
        const int i = (bx-128)*256 + tid;          // < 4096
        const int n = i >> 6, k = i & 63;
        const float w = w1[i];
        const int p = 2*((n & 7)*8 + (n >> 3));
        g_W1d[k*128 + p] = w; g_W1d[k*128 + p + 1] = w;
    } else {
        const int i = (bx-144)*256 + tid;          // < 8192
        const int n = i >> 6, k = i & 63;
        const float w = w2[i];
        const int p = 2*((n & 7)*16 + (n >> 3));
        g_W2d[k*256 + p] = w; g_W2d[k*256 + p + 1] = w;
    }
}

// ======================= FPS block (publishes progress every 64 iters) =======================
__device__ void fps_block(float* __restrict__ out, float* sm, int b)
{
    float* xs = sm;
    float* ys = sm + NPTS;
    float* zs = sm + 2*NPTS;
    uint* wkd = (uint*)(sm + 3*NPTS);   // [2][16]
    uint* wki = wkd + 32;               // [2][16]

    const int tid  = threadIdx.x;       // 512
    const int lane = tid & 31;
    const int warp = tid >> 5;
    const int off = b * NPTS;

    for (int i = tid; i < NPTS; i += 512) {
        xs[i] = g_sx[off + i]; ys[i] = g_sy[off + i]; zs[i] = g_sz[off + i];
    }
    __syncthreads();

    ull nx2[4], ny2[4], nz2[4];
    float dl[8];
#pragma unroll
    for (int jj = 0; jj < 4; ++jj) {
        const int p0 = tid + (2*jj)*512, p1 = tid + (2*jj+1)*512;
        nx2[jj] = pack2(-xs[p0], -xs[p1]);
        ny2[jj] = pack2(-ys[p0], -ys[p1]);
        nz2[jj] = pack2(-zs[p0], -zs[p1]);
    }
#pragma unroll
    for (int j = 0; j < 8; ++j) dl[j] = 1e10f;

    int far = 0, buf = 0;
    for (int it = 0; it < NP; ++it) {
        const float cx = xs[far], cy = ys[far], cz = zs[far];
        const ull cx2 = pack2(cx, cx), cy2 = pack2(cy, cy), cz2 = pack2(cz, cz);
#pragma unroll
        for (int jj = 0; jj < 4; ++jj) {
            const ull dx2 = add2(cx2, nx2[jj]);   // cx + (-x): bit-identical squares
            const ull dy2 = add2(cy2, ny2[jj]);
            const ull dz2 = add2(cz2, nz2[jj]);
            ull dd2 = mul2(dx2, dx2);
            fma2(dd2, dy2, dy2);
            fma2(dd2, dz2, dz2);
            const float2 f = u2f2(dd2);
            dl[2*jj]   = fminf(dl[2*jj],   f.x);
            dl[2*jj+1] = fminf(dl[2*jj+1], f.y);
        }
        if (tid == 0) {
            const int o = (b*NP + it)*3;
            g_nxyz[o+0] = cx; g_nxyz[o+1] = cy; g_nxyz[o+2] = cz;
            out[o+0] = cx;    out[o+1] = cy;    out[o+2] = cz;
            if ((it & 63) == 63) st_rel(&g_prog[b], (uint)(it + 1));  // amortized publish
        }
        const float t01 = fmaxf(dl[0], dl[1]), t23 = fmaxf(dl[2], dl[3]);
        const float t45 = fmaxf(dl[4], dl[5]), t67 = fmaxf(dl[6], dl[7]);
        const float tmax = fmaxf(fmaxf(t01, t23), fmaxf(t45, t67));
        int idx = tid + 7*512;
#pragma unroll
        for (int j = 6; j >= 0; --j) idx = (dl[j] == tmax) ? (tid + j*512) : idx;

        const uint tb   = __float_as_uint(tmax);
        const uint wmax = rmax(tb);
        const uint wi   = rmin((tb == wmax) ? (uint)idx : 0x7fffffffu);
        if (lane == 0) { wkd[buf*16 + warp] = wmax; wki[buf*16 + warp] = wi; }
        __syncthreads();
        const uint dd2v = (lane < 16) ? wkd[buf*16 + lane] : 0u;
        const uint ii2v = (lane < 16) ? wki[buf*16 + lane] : 0x7fffffffu;
        const uint bmax = rmax(dd2v);
        far = (int)rmin((dd2v == bmax) ? ii2v : 0x7fffffffu);
        buf ^= 1;
    }
}

// ======================= fprep chunk =======================
__device__ void fprep_block(const float* __restrict__ pts,
                            const float* __restrict__ W, float* smf, int blk)
{
    float* XsT = smf;               // [67][130]
    float* WtD = smf + 67*130;      // [67][128]
    const int tid = threadIdx.x;    // 512

    __syncthreads();                // protect smem reuse across chunks
    for (int i = tid; i < 67*64; i += 512) {
        const int n = i / 67, k = i - n*67;
        const float w = W[i];
        const int p = 2*((n & 3)*16 + (n >> 2));
        WtD[k*128 + p] = w; WtD[k*128 + p + 1] = w;
    }
    for (int i = tid; i < 128*67; i += 512) {
        const int lr = i / 67, c = i - lr*67;
        const int row = blk*128 + lr;
        float v;
        if (c >= 3)     v = pts[(size_t)row*64 + (c-3)];
        else if (c==0)  v = g_sx[row];
        else if (c==1)  v = g_sy[row];
        else            v = g_sz[row];
        XsT[c*130 + lr] = v;
    }
    __syncthreads();

    const int tx = tid & 15;
    const int ty = tid >> 4;
    ull acc[2][4] = {};
#pragma unroll 4
    for (int k = 0; k < 67; ++k) {
        ull a[2], bv[4];
#pragma unroll
        for (int i2 = 0; i2 < 2; ++i2) a[i2] = *(const ull*)&XsT[k*130 + ty*4 + 2*i2];
#pragma unroll
        for (int j = 0; j < 4; ++j)    bv[j] = *(const ull*)&WtD[k*128 + 2*(j*16 + tx)];
#pragma unroll
        for (int i2 = 0; i2 < 2; ++i2)
#pragma unroll
            for (int j = 0; j < 4; ++j) fma2(acc[i2][j], a[i2], bv[j]);
    }
    const int rbase = blk*128 + ty*4;
#pragma unroll
    for (int i2 = 0; i2 < 2; ++i2) {
        float2 t[4];
#pragma unroll
        for (int j = 0; j < 4; ++j) t[j] = u2f2(acc[i2][j]);
        const int r = rbase + 2*i2;
        *(float4*)&g_F[(size_t)r*64 + tx*4]     = make_float4(t[0].x, t[1].x, t[2].x, t[3].x);
        *(float4*)&g_F[(size_t)(r+1)*64 + tx*4] = make_float4(t[0].y, t[1].y, t[2].y, t[3].y);
    }
}

// ======================= ball query (spins on fps progress) =======================
__device__ void qb_query(int q, int lane)
{
    const int b = q >> 10;
    const int s = q & 1023;
    while (ld_acq(&g_prog[b]) <= (uint)s) __nanosleep(200);

    const int off = b * NPTS;
    const float cx = g_nxyz[q*3+0], cy = g_nxyz[q*3+1], cz = g_nxyz[q*3+2];
    int* g = g_gi + q*NS;

    int cnt = 0, first = -1;
    for (int r = 0; r < NPTS/32; ++r) {
        const int n = r*32 + lane;
        const float dx = g_sx[off+n]-cx, dy = g_sy[off+n]-cy, dz = g_sz[off+n]-cz;
        const float d2 = dx*dx + dy*dy + dz*dz;
        const bool in = (d2 <= RAD2);
        const unsigned m = __ballot_sync(0xFFFFFFFFu, in);
        if (first < 0 && m) first = r*32 + __ffs(m) - 1;
        const int pos = cnt + __popc(m & ((1u << lane) - 1u));
        if (in && pos < NS) g[pos] = n;
        cnt += __popc(m);
        if (cnt >= NS) break;
    }
    for (int i = cnt + lane; i < NS; i += 32) g[i] = first;
}

// ======================= mega: fps (blocks 0-7) + workers (fprep -> qb) =======================
__global__ __launch_bounds__(512) void mega_kernel(const float* __restrict__ pts,
                                                   const float* __restrict__ w0,
                                                   float* __restrict__ out)
{
    extern __shared__ float sm[];
    if (blockIdx.x < 8) {
        fps_block(out, sm, blockIdx.x);
    } else {
        const int w = blockIdx.x - 8;              // 0..119
        for (int c = w; c < 256; c += 120)
            fprep_block(pts, w0, sm, c);
        const int lane = threadIdx.x & 31;
        const int gw = w*16 + (threadIdx.x >> 5);  // 0..1919
        for (int q = gw; q < NQ; q += 1920)
            qb_query(q, lane);
    }
}

// ======================= layer-0 stats (+in-kernel finalize) =======================
__global__ __launch_bounds__(256) void stats0_kernel(const float* __restrict__ w0,
                                                     const float* __restrict__ gam,
                                                     const float* __restrict__ bet)
{
    __shared__ float sw[192];
    __shared__ float sd[256], sq[256];
    __shared__ double fws[512];
    __shared__ bool isLast;
    const int tid = threadIdx.x, blk = blockIdx.x;
    for (int i = tid; i < 192; i += 256) sw[i] = w0[(i/3)*67 + (i%3)];
    __syncthreads();

    const int c = tid & 63, rg = tid >> 6;
    float s = 0.f, q = 0.f;
#pragma unroll 4
    for (int r = rg; r < 128; r += 4) {
        const int row = blk*128 + r;
        const int b = row >> 15;
        const int qg = row >> 5;
        const int idx = g_gi[row];
        const float Cc = g_nxyz[qg*3+0]*sw[c*3+0]
                       + g_nxyz[qg*3+1]*sw[c*3+1]
                       + g_nxyz[qg*3+2]*sw[c*3+2];
        const float v = g_F[(((size_t)b << 12) + idx)*64 + c] - Cc;
        s += v; q = fmaf(v, v, q);
    }
    sd[tid] = s; sq[tid] = q;
    __syncthreads();
    if (tid < 64) {
        g_p0[blk*64 + tid] = make_float2(sd[tid] + sd[64+tid] + sd[128+tid] + sd[192+tid],
                                         sq[tid] + sq[64+tid] + sq[128+tid] + sq[192+tid]);
    }
    __threadfence();
    if (tid == 0) isLast = (atomicAdd(&g_ctr[0], 1u) == 2047u);
    __syncthreads();
    if (isLast) {
        __threadfence();
        finalize_inblock<64, 2048, 256>(g_p0, gam, bet, g_sc0, g_sh0, fws);
    }
}

// ======================= mm1 (pipelined, +in-kernel finalize) =======================
__global__ __launch_bounds__(128, 2) void mm1_kernel(const float* __restrict__ w0,
                                                     const float* __restrict__ gam,
                                                     const float* __restrict__ bet)
{
    extern __shared__ float smf[];
    float* XsT  = smf;              // [64][258]
    float* WtD  = smf + 64*258;     // [64][128]
    float* ssum = WtD;              // alias post-GEMM [16][64]
    float* ssq  = WtD + 16*64;
    double* fws = (double*)(WtD + 32*64);   // 256 doubles fit in remaining 24KB
    __shared__ float sW0x[192];
    __shared__ float sCtr[24];
    __shared__ int   sIdx[256];
    __shared__ bool  isLast;

    const int tid = threadIdx.x, blk = blockIdx.x;

    for (int i = tid; i < 64*128/4; i += 128)
        ((float4*)WtD)[i] = ((const float4*)g_W1d)[i];
    for (int i = tid; i < 192; i += 128) sW0x[i] = w0[(i/3)*67 + (i%3)];
    if (tid < 24) sCtr[tid] = g_nxyz[(blk*8 + tid/3)*3 + (tid%3)];
    for (int i = tid; i < 256; i += 128) sIdx[i] = g_gi[blk*256 + i];
    __syncthreads();

    const int bb = blk >> 7;
    for (int i = tid; i < 256*64; i += 128) {
        const int lr = i >> 6, c = i & 63;
        const int g = lr >> 5;
        const int idx = sIdx[lr];
        const float Cc = sCtr[g*3+0]*sW0x[c*3+0]
                       + sCtr[g*3+1]*sW0x[c*3+1]
                       + sCtr[g*3+2]*sW0x[c*3+2];
        float v = g_F[(((size_t)bb << 12) + idx)*64 + c] - Cc;
        v = fmaxf(fmaf(v, g_sc0[c], g_sh0[c]), 0.f);
        XsT[c*258 + lr] = v;
    }
    __syncthreads();

    const int tx = tid & 7, ty = tid >> 3;
    const int arow = ty*16;
    ull acc[8][8] = {};
    ull aC[8], bC[8], aN[8], bN[8];
#pragma unroll
    for (int i2 = 0; i2 < 8; ++i2) aC[i2] = *(const ull*)&XsT[arow + 2*i2];
#pragma unroll
    for (int j = 0; j < 8; ++j)    bC[j] = *(const ull*)&WtD[2*(j*8 + tx)];
#pragma unroll 1
    for (int k = 0; k < 62; k += 2) {
#pragma unroll
        for (int i2 = 0; i2 < 8; ++i2) aN[i2] = *(const ull*)&XsT[(k+1)*258 + arow + 2*i2];
#pragma unroll
        for (int j = 0; j < 8; ++j)    bN[j] = *(const ull*)&WtD[(k+1)*128 + 2*(j*8 + tx)];
#pragma unroll
        for (int i2 = 0; i2 < 8; ++i2)
#pragma unroll
            for (int j = 0; j < 8; ++j) fma2(acc[i2][j], aC[i2], bC[j]);
#pragma unroll
        for (int i2 = 0; i2 < 8; ++i2) aC[i2] = *(const ull*)&XsT[(k+2)*258 + arow + 2*i2];
#pragma unroll
        for (int j = 0; j < 8; ++j)    bC[j] = *(const ull*)&WtD[(k+2)*128 + 2*(j*8 + tx)];
#pragma unroll
        for (int i2 = 0; i2 < 8; ++i2)
#pragma unroll
            for (int j = 0; j < 8; ++j) fma2(acc[i2][j], aN[i2], bN[j]);
    }
#pragma unroll
    for (int i2 = 0; i2 < 8; ++i2) aN[i2] = *(const ull*)&XsT[63*258 + arow + 2*i2];
#pragma unroll
    for (int j = 0; j < 8; ++j)    bN[j] = *(const ull*)&WtD[63*128 + 2*(j*8 + tx)];
#pragma unroll
    for (int i2 = 0; i2 < 8; ++i2)
#pragma unroll
        for (int j = 0; j < 8; ++j) fma2(acc[i2][j], aC[i2], bC[j]);
#pragma unroll
    for (int i2 = 0; i2 < 8; ++i2)
#pragma unroll
        for (int j = 0; j < 8; ++j) fma2(acc[i2][j], aN[i2], bN[j]);

    float ls[8], lq[8];
#pragma unroll
    for (int j = 0; j < 8; ++j) {
        float s = 0.f, q = 0.f;
#pragma unroll
        for (int i2 = 0; i2 < 8; ++i2) {
            const float2 v = u2f2(acc[i2][j]);
            s += v.x; s += v.y;
            q = fmaf(v.x, v.x, q); q = fmaf(v.y, v.y, q);
        }
        ls[j] = s; lq[j] = q;
    }
    const int rbase = blk*256 + ty*16;
#pragma unroll
    for (int i2 = 0; i2 < 8; ++i2) {
        float2 t[8];
#pragma unroll
        for (int j = 0; j < 8; ++j) t[j] = u2f2(acc[i2][j]);
        const int r = rbase + 2*i2;
        float* y0 = &g_Y1[(size_t)r*64 + tx*8];
        ((float4*)y0)[0] = make_float4(t[0].x, t[1].x, t[2].x, t[3].x);
        ((float4*)y0)[1] = make_float4(t[4].x, t[5].x, t[6].x, t[7].x);
        float* y1 = &g_Y1[(size_t)(r+1)*64 + tx*8];
        ((float4*)y1)[0] = make_float4(t[0].y, t[1].y, t[2].y, t[3].y);
        ((float4*)y1)[1] = make_float4(t[4].y, t[5].y, t[6].y, t[7].y);
    }
    __syncthreads();
#pragma unroll
    for (int j = 0; j < 8; ++j) {
        ssum[ty*64 + tx*8 + j] = ls[j];
        ssq [ty*64 + tx*8 + j] = lq[j];
    }
    __syncthreads();
    if (tid < 64) {
        float s = 0.f, q = 0.f;
#pragma unroll
        for (int t = 0; t < 16; ++t) { s += ssum[t*64 + tid]; q += ssq[t*64 + tid]; }
        g_p1[blk*64 + tid] = make_float2(s, q);
    }
    __threadfence();
    if (tid == 0) isLast = (atomicAdd(&g_ctr[1], 1u) == 1023u);
    __syncthreads();
    if (isLast) {
        __threadfence();
        finalize_inblock<64, 1024, 128>(g_p1, gam, bet, g_sc1, g_sh1, fws);
    }
}

// ======================= mm2 (pipelined, +stats +max-pool +in-kernel finalize) =======================
__global__ __launch_bounds__(128, 2) void mm2_kernel(const float* __restrict__ gam,
                                                     const float* __restrict__ bet)
{
    extern __shared__ float smf[];
    float* XsT  = smf;              // [64][130]
    float* WtD  = smf + 64*130;     // [64][256]
    float* ssum = WtD;              // alias [8][128]
    float* ssq  = WtD + 8*128;
    float* smax = WtD + 16*128;
    double* fws = (double*)(WtD + 24*128);   // 256 doubles, within WtD's 64KB
    __shared__ bool isLast;

    const int tid = threadIdx.x, blk = blockIdx.x;

    for (int i = tid; i < 64*256/4; i += 128)
        ((float4*)WtD)[i] = ((const float4*)g_W2d)[i];
    for (int i = tid; i < 128*64; i += 128) {
        const int lr = i >> 6, c = i & 63;
        float v = g_Y1[((size_t)blk*128 + lr)*64 + c];
        v = fmaxf(fmaf(v, g_sc1[c], g_sh1[c]), 0.f);
        XsT[c*130 + lr] = v;
    }
    __syncthreads();

    const int tx = tid & 15, ty = tid >> 4;
    const int arow = ty*16;
    ull acc[8][8] = {};
    ull aC[8], bC[8], aN[8], bN[8];
#pragma unroll
    for (int i2 = 0; i2 < 8; ++i2) aC[i2] = *(const ull*)&XsT[arow + 2*i2];
#pragma unroll
    for (int j = 0; j < 8; ++j)    bC[j] = *(const ull*)&WtD[2*(j*16 + tx)];
#pragma unroll 1
    for (int k = 0; k < 62; k += 2) {
#pragma unroll
        for (int i2 = 0; i2 < 8; ++i2) aN[i2] = *(const ull*)&XsT[(k+1)*130 + arow + 2*i2];
#pragma unroll
        for (int j = 0; j < 8; ++j)    bN[j] = *(const ull*)&WtD[(k+1)*256 + 2*(j*16 + tx)];
#pragma unroll
        for (int i2 = 0; i2 < 8; ++i2)
#pragma unroll
            for (int j = 0; j < 8; ++j) fma2(acc[i2][j], aC[i2], bC[j]);
#pragma unroll
        for (int i2 = 0; i2 < 8; ++i2) aC[i2] = *(const ull*)&XsT[(k+2)*130 + arow + 2*i2];
#pragma unroll
        for (int j = 0; j < 8; ++j)    bC[j] = *(const ull*)&WtD[(k+2)*256 + 2*(j*16 + tx)];
#pragma unroll
        for (int i2 = 0; i2 < 8; ++i2)
#pragma unroll
            for (int j = 0; j < 8; ++j) fma2(acc[i2][j], aN[i2], bN[j]);
    }
#pragma unroll
    for (int i2 = 0; i2 < 8; ++i2) aN[i2] = *(const ull*)&XsT[63*130 + arow + 2*i2];
#pragma unroll
    for (int j = 0; j < 8; ++j)    bN[j] = *(const ull*)&WtD[63*256 + 2*(j*16 + tx)];
#pragma unroll
    for (int i2 = 0; i2 < 8; ++i2)
#pragma unroll
        for (int j = 0; j < 8; ++j) fma2(acc[i2][j], aC[i2], bC[j]);
#pragma unroll
    for (int i2 = 0; i2 < 8; ++i2)
#pragma unroll
        for (int j = 0; j < 8; ++j) fma2(acc[i2][j], aN[i2], bN[j]);

    float ls[8], lq[8], lm[8];
#pragma unroll
    for (int j = 0; j < 8; ++j) {
        float s = 0.f, q = 0.f, m = -3.4e38f;
#pragma unroll
        for (int i2 = 0; i2 < 8; ++i2) {
            const float2 v = u2f2(acc[i2][j]);
            s += v.x; s += v.y;
            q = fmaf(v.x, v.x, q); q = fmaf(v.y, v.y, q);
            m = fmaxf(m, fmaxf(v.x, v.y));
        }
        ls[j] = s; lq[j] = q; lm[j] = m;
    }
    __syncthreads();
#pragma unroll
    for (int j = 0; j < 8; ++j) {
        const int c = tx*8 + j;
        ssum[ty*128 + c] = ls[j];
        ssq [ty*128 + c] = lq[j];
        smax[ty*128 + c] = lm[j];
    }
    __syncthreads();
    if (tid < 128) {
        float s = 0.f, q = 0.f;
#pragma unroll
        for (int t = 0; t < 8; ++t) { s += ssum[t*128 + tid]; q += ssq[t*128 + tid]; }
        g_p2[blk*128 + tid] = make_float2(s, q);
    }
    for (int w = tid; w < 512; w += 128) {
        const int g = w >> 7, c = w & 127;
        const float m = fmaxf(smax[(2*g)*128 + c], smax[(2*g+1)*128 + c]);
        g_max[(blk*4 + g)*128 + c] = m;
    }
    __threadfence();
    if (tid == 0) isLast = (atomicAdd(&g_ctr[2], 1u) == 2047u);
    __syncthreads();
    if (isLast) {
        __threadfence();
        finalize_inblock<128, 2048, 128>(g_p2, gam, bet, g_sc2, g_sh2, fws);
    }
}

// ======================= final pool =======================
__global__ void pool_kernel(float* __restrict__ out)
{
    const int i = blockIdx.x * 1024 + threadIdx.x;
    const int c = i & 127;
    out[NQ*3 + i] = fmaxf(fmaf(g_max[i], g_sc2[c], g_sh2[c]), 0.f);
}

// ======================= launch =======================
extern "C" void kernel_launch(void* const* d_in, const int* in_sizes, int n_in,
                              void* d_out, int out_size)
{
    const float* xyz = (const float*)d_in[0];
    const float* pts = (const float*)d_in[1];
    const float* w0  = (const float*)d_in[2];
    const float* gm0 = (const float*)d_in[4];
    const float* bt0 = (const float*)d_in[5];
    const float* w1  = (const float*)d_in[6];
    const float* gm1 = (const float*)d_in[8];
    const float* bt1 = (const float*)d_in[9];
    const float* w2  = (const float*)d_in[10];
    const float* gm2 = (const float*)d_in[12];
    const float* bt2 = (const float*)d_in[13];
    float* out = (float*)d_out;

    const int smFU = 67*130*4 + 67*128*4;   // 69144
    const int smM1 = 64*258*4 + 64*128*4;   // 98816
    const int smM2 = 64*130*4 + 64*256*4;   // 98816

    cudaFuncSetAttribute(mega_kernel, cudaFuncAttributeMaxDynamicSharedMemorySize, smFU);
    cudaFuncSetAttribute(mm1_kernel, cudaFuncAttributeMaxDynamicSharedMemorySize, smM1);
    cudaFuncSetAttribute(mm2_kernel, cudaFuncAttributeMaxDynamicSharedMemorySize, smM2);

    prep_kernel<<<176, 256>>>(xyz, w1, w2);                    // idx 0
    mega_kernel<<<128, 512, smFU>>>(pts, w0, out);             // idx 1
    stats0_kernel<<<2048, 256>>>(w0, gm0, bt0);                // idx 2
    mm1_kernel<<<MROWS/256, 128, smM1>>>(w0, gm1, bt1);        // idx 3 (profiled)
    mm2_kernel<<<MROWS/128, 128, smM2>>>(gm2, bt2);            // idx 4
    pool_kernel<<<(NQ*128)/1024, 1024>>>(out);                 // idx 5
}

// round 14
// speedup vs baseline: 1.3825x; 1.3825x over previous
#include <cuda_runtime.h>

#define BATCH   8
#define NPTS    4096
#define NP      1024
#define NS      32
#define MROWS   262144
#define NQ      8192
#define NSRC    32768
#define RAD2    0.04f

typedef unsigned long long ull;
typedef unsigned int uint;

// ---------------- device scratch ----------------
__device__ float  g_F[NSRC*64];
__device__ float  g_Y1[(size_t)MROWS*64];
__device__ float  g_max[NQ*128];
__device__ float  g_nxyz[NQ*3];
__device__ int    g_gi[MROWS];
__device__ float2 g_p0[2048*64];
__device__ float2 g_p1[1024*64];
__device__ float2 g_p2[2048*128];
__device__ float  g_sc0[64], g_sh0[64];
__device__ float  g_sc1[64], g_sh1[64];
__device__ float  g_sc2[128], g_sh2[128];
__device__ float  g_sx[NSRC], g_sy[NSRC], g_sz[NSRC];
__device__ float  g_W1d[64*128];
__device__ float  g_W2d[64*256];
__device__ uint   g_ctr[3];

// ---------------- helpers ----------------
__device__ __forceinline__ void fma2(ull& d, ull a, ull b) {
    asm("fma.rn.f32x2 %0, %1, %2, %0;" : "+l"(d) : "l"(a), "l"(b));
}
__device__ __forceinline__ ull mul2(ull a, ull b) {
    ull d; asm("mul.rn.f32x2 %0, %1, %2;" : "=l"(d) : "l"(a), "l"(b)); return d;
}
__device__ __forceinline__ ull add2(ull a, ull b) {
    ull d; asm("add.rn.f32x2 %0, %1, %2;" : "=l"(d) : "l"(a), "l"(b)); return d;
}
__device__ __forceinline__ ull pack2(float lo, float hi) {
    ull d; asm("mov.b64 %0, {%1, %2};" : "=l"(d) : "f"(lo), "f"(hi)); return d;
}
__device__ __forceinline__ float2 u2f2(ull v) {
    float2 r; asm("mov.b64 {%0, %1}, %2;" : "=f"(r.x), "=f"(r.y) : "l"(v)); return r;
}
__device__ __forceinline__ uint rmax(uint v) {
    uint r; asm("redux.sync.max.u32 %0, %1, 0xffffffff;" : "=r"(r) : "r"(v)); return r;
}
__device__ __forceinline__ uint rmin(uint v) {
    uint r; asm("redux.sync.min.u32 %0, %1, 0xffffffff;" : "=r"(r) : "r"(v)); return r;
}

// ---------------- in-kernel BN finalize (deterministic last-block) ----------------
template<int C, int NB, int TPB>
__device__ void finalize_inblock(const float2* __restrict__ part,
                                 const float* __restrict__ gam,
                                 const float* __restrict__ bet,
                                 float* __restrict__ sc, float* __restrict__ sh,
                                 double* ws)   // 2*TPB doubles
{
    constexpr int PERC = TPB / C;
    double* fsd = ws;
    double* fsq = ws + TPB;
    const int tid = threadIdx.x;
    const int c = tid % C, rg = tid / C;
    double s = 0.0, q = 0.0;
    for (int i = rg; i < NB; i += PERC) {
        const float2 v = part[i*C + c];
        s += (double)v.x; q += (double)v.y;
    }
    fsd[tid] = s; fsq[tid] = q;
    __syncthreads();
    if (tid < C) {
        double ts = 0.0, tq = 0.0;
#pragma unroll
        for (int g = 0; g < PERC; ++g) { ts += fsd[g*C + tid]; tq += fsq[g*C + tid]; }
        const double mu  = ts / (double)MROWS;
        const double var = tq / (double)MROWS - mu*mu;
        const float rs = (float)rsqrt(var + 1e-5);
        const float scv = gam[tid] * rs;
        sc[tid] = scv;
        sh[tid] = bet[tid] - (float)mu * scv;
    }
}

// ======================= prep: SoA + weight permutation + counter reset =======================
__global__ __launch_bounds__(256) void prep_kernel(const float* __restrict__ xyz,
                                                   const float* __restrict__ w1,
                                                   const float* __restrict__ w2)
{
    const int tid = threadIdx.x, bx = blockIdx.x;
    if (bx < 128) {
        const int i = bx*256 + tid;
        const float x = xyz[i*3+0], y = xyz[i*3+1], z = xyz[i*3+2];
        g_sx[i] = x; g_sy[i] = y; g_sz[i] = z;
        if (bx == 0 && tid < 3) g_ctr[tid] = 0;
    } else if (bx < 144) {
        const int i = (bx-128)*256 + tid;          // < 4096
        const int n = i >> 6, k = i & 63;
        const float w = w1[i];
        const int p = 2*((n & 7)*8 + (n >> 3));
        g_W1d[k*128 + p] = w; g_W1d[k*128 + p + 1] = w;
    } else {
        const int i = (bx-144)*256 + tid;          // < 8192
        const int n = i >> 6, k = i & 63;
        const float w = w2[i];
        const int p = 2*((n & 7)*16 + (n >> 3));
        g_W2d[k*256 + p] = w; g_W2d[k*256 + p + 1] = w;
    }
}

// ======================= 1a) FPS (register-resident, f32x2 update) =======================
__device__ void fps_block(float* __restrict__ out, float* sm, int b)
{
    float* xs = sm;
    float* ys = sm + NPTS;
    float* zs = sm + 2*NPTS;
    uint* wkd = (uint*)(sm + 3*NPTS);   // [2][16]
    uint* wki = wkd + 32;               // [2][16]

    const int tid  = threadIdx.x;       // 512
    const int lane = tid & 31;
    const int warp = tid >> 5;
    const int off = b * NPTS;

    for (int i = tid; i < NPTS; i += 512) {
        xs[i] = g_sx[off + i]; ys[i] = g_sy[off + i]; zs[i] = g_sz[off + i];
    }
    __syncthreads();

    ull nx2[4], ny2[4], nz2[4];
    float dl[8];
#pragma unroll
    for (int jj = 0; jj < 4; ++jj) {
        const int p0 = tid + (2*jj)*512, p1 = tid + (2*jj+1)*512;
        nx2[jj] = pack2(-xs[p0], -xs[p1]);
        ny2[jj] = pack2(-ys[p0], -ys[p1]);
        nz2[jj] = pack2(-zs[p0], -zs[p1]);
    }
#pragma unroll
    for (int j = 0; j < 8; ++j) dl[j] = 1e10f;

    int far = 0, buf = 0;
    for (int it = 0; it < NP; ++it) {
        const float cx = xs[far], cy = ys[far], cz = zs[far];
        const ull cx2 = pack2(cx, cx), cy2 = pack2(cy, cy), cz2 = pack2(cz, cz);
#pragma unroll
        for (int jj = 0; jj < 4; ++jj) {
            const ull dx2 = add2(cx2, nx2[jj]);   // cx + (-x): bit-identical squares
            const ull dy2 = add2(cy2, ny2[jj]);
            const ull dz2 = add2(cz2, nz2[jj]);
            ull dd2 = mul2(dx2, dx2);
            fma2(dd2, dy2, dy2);
            fma2(dd2, dz2, dz2);
            const float2 f = u2f2(dd2);
            dl[2*jj]   = fminf(dl[2*jj],   f.x);
            dl[2*jj+1] = fminf(dl[2*jj+1], f.y);
        }
        if (tid == 0) {
            const int o = (b*NP + it)*3;
            g_nxyz[o+0] = cx; g_nxyz[o+1] = cy; g_nxyz[o+2] = cz;
            out[o+0] = cx;    out[o+1] = cy;    out[o+2] = cz;
        }
        const float t01 = fmaxf(dl[0], dl[1]), t23 = fmaxf(dl[2], dl[3]);
        const float t45 = fmaxf(dl[4], dl[5]), t67 = fmaxf(dl[6], dl[7]);
        const float tmax = fmaxf(fmaxf(t01, t23), fmaxf(t45, t67));
        int idx = tid + 7*512;
#pragma unroll
        for (int j = 6; j >= 0; --j) idx = (dl[j] == tmax) ? (tid + j*512) : idx;

        const uint tb   = __float_as_uint(tmax);
        const uint wmax = rmax(tb);
        const uint wi   = rmin((tb == wmax) ? (uint)idx : 0x7fffffffu);
        if (lane == 0) { wkd[buf*16 + warp] = wmax; wki[buf*16 + warp] = wi; }
        __syncthreads();
        const uint dd2v = (lane < 16) ? wkd[buf*16 + lane] : 0u;
        const uint ii2v = (lane < 16) ? wki[buf*16 + lane] : 0x7fffffffu;
        const uint bmax = rmax(dd2v);
        far = (int)rmin((dd2v == bmax) ? ii2v : 0x7fffffffu);
        buf ^= 1;
    }
}

// ======================= 1b) fprep: F = concat(xyz, pts) @ W0^T =======================
__device__ void fprep_block(const float* __restrict__ pts,
                            const float* __restrict__ W, float* smf, int blk)
{
    float* XsT = smf;               // [67][130]
    float* WtD = smf + 67*130;      // [67][128]
    const int tid = threadIdx.x;    // 512

    for (int i = tid; i < 67*64; i += 512) {
        const int n = i / 67, k = i - n*67;
        const float w = W[i];
        const int p = 2*((n & 3)*16 + (n >> 2));
        WtD[k*128 + p] = w; WtD[k*128 + p + 1] = w;
    }
    for (int i = tid; i < 128*67; i += 512) {
        const int lr = i / 67, c = i - lr*67;
        const int row = blk*128 + lr;
        float v;
        if (c >= 3)     v = pts[(size_t)row*64 + (c-3)];
        else if (c==0)  v = g_sx[row];
        else if (c==1)  v = g_sy[row];
        else            v = g_sz[row];
        XsT[c*130 + lr] = v;
    }
    __syncthreads();

    const int tx = tid & 15;
    const int ty = tid >> 4;
    ull acc[2][4] = {};
#pragma unroll 4
    for (int k = 0; k < 67; ++k) {
        ull a[2], bv[4];
#pragma unroll
        for (int i2 = 0; i2 < 2; ++i2) a[i2] = *(const ull*)&XsT[k*130 + ty*4 + 2*i2];
#pragma unroll
        for (int j = 0; j < 4; ++j)    bv[j] = *(const ull*)&WtD[k*128 + 2*(j*16 + tx)];
#pragma unroll
        for (int i2 = 0; i2 < 2; ++i2)
#pragma unroll
            for (int j = 0; j < 4; ++j) fma2(acc[i2][j], a[i2], bv[j]);
    }
    const int rbase = blk*128 + ty*4;
#pragma unroll
    for (int i2 = 0; i2 < 2; ++i2) {
        float2 t[4];
#pragma unroll
        for (int j = 0; j < 4; ++j) t[j] = u2f2(acc[i2][j]);
        const int r = rbase + 2*i2;
        *(float4*)&g_F[(size_t)r*64 + tx*4]     = make_float4(t[0].x, t[1].x, t[2].x, t[3].x);
        *(float4*)&g_F[(size_t)(r+1)*64 + tx*4] = make_float4(t[0].y, t[1].y, t[2].y, t[3].y);
    }
}

__global__ __launch_bounds__(512) void fused_fps_fprep(const float* __restrict__ pts,
                                                       const float* __restrict__ w0,
                                                       float* __restrict__ out)
{
    extern __shared__ float sm[];
    if (blockIdx.x < 8) fps_block(out, sm, blockIdx.x);
    else                fprep_block(pts, w0, sm, blockIdx.x - 8);
}

// ======================= 2) stats0: local ball-query + layer-0 stats + finalize0 =======================
__global__ __launch_bounds__(256) void stats0_kernel(const float* __restrict__ w0,
                                                     const float* __restrict__ gam,
                                                     const float* __restrict__ bet)
{
    __shared__ float sw[192];
    __shared__ float sd[256], sq[256];
    __shared__ int   sIdxS[128];
    __shared__ double fws[512];
    __shared__ bool  isLast;
    const int tid = threadIdx.x, blk = blockIdx.x;
    const int lane = tid & 31, warp = tid >> 5;
    for (int i = tid; i < 192; i += 256) sw[i] = w0[(i/3)*67 + (i%3)];

    // ---- ball query for this block's 4 queries (warps 0-3) ----
    if (warp < 4) {
        const int q = blk*4 + warp;
        const int b = q >> 10;
        const int off = b * NPTS;
        const float cx = g_nxyz[q*3+0], cy = g_nxyz[q*3+1], cz = g_nxyz[q*3+2];
        int* g = g_gi + q*NS;
        int cnt = 0, first = -1;
        for (int r = 0; r < NPTS/32; ++r) {
            const int n = r*32 + lane;
            const float dx = g_sx[off+n]-cx, dy = g_sy[off+n]-cy, dz = g_sz[off+n]-cz;
            const float d2 = dx*dx + dy*dy + dz*dz;
            const bool in = (d2 <= RAD2);
            const unsigned m = __ballot_sync(0xFFFFFFFFu, in);
            if (first < 0 && m) first = r*32 + __ffs(m) - 1;
            const int pos = cnt + __popc(m & ((1u << lane) - 1u));
            if (in && pos < NS) { g[pos] = n; sIdxS[warp*32 + pos] = n; }
            cnt += __popc(m);
            if (cnt >= NS) break;
        }
        for (int i = cnt + lane; i < NS; i += 32) { g[i] = first; sIdxS[warp*32 + i] = first; }
    }
    __syncthreads();

    // ---- stats over this block's 128 rows ----
    const int c = tid & 63, rg = tid >> 6;
    float s = 0.f, q = 0.f;
#pragma unroll 4
    for (int r = rg; r < 128; r += 4) {
        const int row = blk*128 + r;
        const int b = row >> 15;
        const int qg = row >> 5;
        const int idx = sIdxS[r];
        const float Cc = g_nxyz[qg*3+0]*sw[c*3+0]
                       + g_nxyz[qg*3+1]*sw[c*3+1]
                       + g_nxyz[qg*3+2]*sw[c*3+2];
        const float v = g_F[(((size_t)b << 12) + idx)*64 + c] - Cc;
        s += v; q = fmaf(v, v, q);
    }
    sd[tid] = s; sq[tid] = q;
    __syncthreads();
    if (tid < 64) {
        g_p0[blk*64 + tid] = make_float2(sd[tid] + sd[64+tid] + sd[128+tid] + sd[192+tid],
                                         sq[tid] + sq[64+tid] + sq[128+tid] + sq[192+tid]);
    }
    __threadfence();
    if (tid == 0) isLast = (atomicAdd(&g_ctr[0], 1u) == 2047u);
    __syncthreads();
    if (isLast) {
        __threadfence();
        finalize_inblock<64, 2048, 256>(g_p0, gam, bet, g_sc0, g_sh0, fws);
    }
}

// ======================= 3) mm1 (R12 body, unroll 2, +finalize1) =======================
__global__ __launch_bounds__(128, 2) void mm1_kernel(const float* __restrict__ w0,
                                                     const float* __restrict__ gam,
                                                     const float* __restrict__ bet)
{
    extern __shared__ float smf[];
    float* XsT  = smf;              // [64][258]
    float* WtD  = smf + 64*258;     // [64][128]
    float* ssum = WtD;              // alias post-GEMM [16][64]
    float* ssq  = WtD + 16*64;
    double* fws = (double*)(WtD + 2048);   // 256 doubles, after ssum/ssq
    __shared__ float sW0x[192];
    __shared__ float sCtr[24];
    __shared__ int   sIdx[256];
    __shared__ bool  isLast;

    const int tid = threadIdx.x, blk = blockIdx.x;

    for (int i = tid; i < 64*128/4; i += 128)
        ((float4*)WtD)[i] = ((const float4*)g_W1d)[i];
    for (int i = tid; i < 192; i += 128) sW0x[i] = w0[(i/3)*67 + (i%3)];
    if (tid < 24) sCtr[tid] = g_nxyz[(blk*8 + tid/3)*3 + (tid%3)];
    for (int i = tid; i < 256; i += 128) sIdx[i] = g_gi[blk*256 + i];
    __syncthreads();

    const int bb = blk >> 7;
    for (int i = tid; i < 256*64; i += 128) {
        const int lr = i >> 6, c = i & 63;
        const int g = lr >> 5;
        const int idx = sIdx[lr];
        const float Cc = sCtr[g*3+0]*sW0x[c*3+0]
                       + sCtr[g*3+1]*sW0x[c*3+1]
                       + sCtr[g*3+2]*sW0x[c*3+2];
        float v = g_F[(((size_t)bb << 12) + idx)*64 + c] - Cc;
        v = fmaxf(fmaf(v, g_sc0[c], g_sh0[c]), 0.f);
        XsT[c*258 + lr] = v;
    }
    __syncthreads();

    const int tx = tid & 7, ty = tid >> 3;
    ull acc[8][8] = {};
#pragma unroll 2
    for (int k = 0; k < 64; ++k) {
        ull a[8], bv[8];
#pragma unroll
        for (int i2 = 0; i2 < 8; ++i2) a[i2] = *(const ull*)&XsT[k*258 + ty*16 + 2*i2];
#pragma unroll
        for (int j = 0; j < 8; ++j)    bv[j] = *(const ull*)&WtD[k*128 + 2*(j*8 + tx)];
#pragma unroll
        for (int i2 = 0; i2 < 8; ++i2)
#pragma unroll
            for (int j = 0; j < 8; ++j) fma2(acc[i2][j], a[i2], bv[j]);
    }

    float ls[8], lq[8];
#pragma unroll
    for (int j = 0; j < 8; ++j) {
        float s = 0.f, q = 0.f;
#pragma unroll
        for (int i2 = 0; i2 < 8; ++i2) {
            const float2 v = u2f2(acc[i2][j]);
            s += v.x; s += v.y;
            q = fmaf(v.x, v.x, q); q = fmaf(v.y, v.y, q);
        }
        ls[j] = s; lq[j] = q;
    }
    const int rbase = blk*256 + ty*16;
#pragma unroll
    for (int i2 = 0; i2 < 8; ++i2) {
        float2 t[8];
#pragma unroll
        for (int j = 0; j < 8; ++j) t[j] = u2f2(acc[i2][j]);
        const int r = rbase + 2*i2;
        float* y0 = &g_Y1[(size_t)r*64 + tx*8];
        ((float4*)y0)[0] = make_float4(t[0].x, t[1].x, t[2].x, t[3].x);
        ((float4*)y0)[1] = make_float4(t[4].x, t[5].x, t[6].x, t[7].x);
        float* y1 = &g_Y1[(size_t)(r+1)*64 + tx*8];
        ((float4*)y1)[0] = make_float4(t[0].y, t[1].y, t[2].y, t[3].y);
        ((float4*)y1)[1] = make_float4(t[4].y, t[5].y, t[6].y, t[7].y);
    }
    __syncthreads();
#pragma unroll
    for (int j = 0; j < 8; ++j) {
        ssum[ty*64 + tx*8 + j] = ls[j];
        ssq [ty*64 + tx*8 + j] = lq[j];
    }
    __syncthreads();
    if (tid < 64) {
        float s = 0.f, q = 0.f;
#pragma unroll
        for (int t = 0; t < 16; ++t) { s += ssum[t*64 + tid]; q += ssq[t*64 + tid]; }
        g_p1[blk*64 + tid] = make_float2(s, q);
    }
    __threadfence();
    if (tid == 0) isLast = (atomicAdd(&g_ctr[1], 1u) == 1023u);
    __syncthreads();
    if (isLast) {
        __threadfence();
        finalize_inblock<64, 1024, 128>(g_p1, gam, bet, g_sc1, g_sh1, fws);
    }
}

// ======================= 4) mm2 (R12 body, unroll 2, +stats +max-pool) =======================
__global__ __launch_bounds__(128, 2) void mm2_kernel()
{
    extern __shared__ float smf[];
    float* XsT  = smf;              // [64][130]
    float* WtD  = smf + 64*130;     // [64][256]
    float* ssum = WtD;              // alias [8][128]
    float* ssq  = WtD + 8*128;
    float* smax = WtD + 16*128;

    const int tid = threadIdx.x, blk = blockIdx.x;

    for (int i = tid; i < 64*256/4; i += 128)
        ((float4*)WtD)[i] = ((const float4*)g_W2d)[i];
    for (int i = tid; i < 128*64; i += 128) {
        const int lr = i >> 6, c = i & 63;
        float v = g_Y1[((size_t)blk*128 + lr)*64 + c];
        v = fmaxf(fmaf(v, g_sc1[c], g_sh1[c]), 0.f);
        XsT[c*130 + lr] = v;
    }
    __syncthreads();

    const int tx = tid & 15, ty = tid >> 4;
    ull acc[8][8] = {};
#pragma unroll 2
    for (int k = 0; k < 64; ++k) {
        ull a[8], bv[8];
#pragma unroll
        for (int i2 = 0; i2 < 8; ++i2) a[i2] = *(const ull*)&XsT[k*130 + ty*16 + 2*i2];
#pragma unroll
        for (int j = 0; j < 8; ++j)    bv[j] = *(const ull*)&WtD[k*256 + 2*(j*16 + tx)];
#pragma unroll
        for (int i2 = 0; i2 < 8; ++i2)
#pragma unroll
            for (int j = 0; j < 8; ++j) fma2(acc[i2][j], a[i2], bv[j]);
    }

    float ls[8], lq[8], lm[8];
#pragma unroll
    for (int j = 0; j < 8; ++j) {
        float s = 0.f, q = 0.f, m = -3.4e38f;
#pragma unroll
        for (int i2 = 0; i2 < 8; ++i2) {
            const float2 v = u2f2(acc[i2][j]);
            s += v.x; s += v.y;
            q = fmaf(v.x, v.x, q); q = fmaf(v.y, v.y, q);
            m = fmaxf(m, fmaxf(v.x, v.y));
        }
        ls[j] = s; lq[j] = q; lm[j] = m;
    }
    __syncthreads();
#pragma unroll
    for (int j = 0; j < 8; ++j) {
        const int c = tx*8 + j;
        ssum[ty*128 + c] = ls[j];
        ssq [ty*128 + c] = lq[j];
        smax[ty*128 + c] = lm[j];
    }
    __syncthreads();
    if (tid < 128) {
        float s = 0.f, q = 0.f;
#pragma unroll
        for (int t = 0; t < 8; ++t) { s += ssum[t*128 + tid]; q += ssq[t*128 + tid]; }
        g_p2[blk*128 + tid] = make_float2(s, q);
    }
    for (int w = tid; w < 512; w += 128) {
        const int g = w >> 7, c = w & 127;
        const float m = fmaxf(smax[(2*g)*128 + c], smax[(2*g+1)*128 + c]);
        g_max[(blk*4 + g)*128 + c] = m;
    }
}

// ======================= finalize BN (layer 2 only) =======================
__global__ void finalize_kernel(int layer, int nblk,
                                const float* __restrict__ gam,
                                const float* __restrict__ bet)
{
    const float2* part = g_p2;
    const int C = 128;
    const int c = blockIdx.x;
    const int tid = threadIdx.x;
    __shared__ double sd[256], sq[256];
    double s = 0.0, q = 0.0;
    for (int i = tid; i < nblk; i += 256) {
        const float2 v = part[i*C + c];
        s += (double)v.x; q += (double)v.y;
    }
    sd[tid] = s; sq[tid] = q;
    __syncthreads();
    for (int off = 128; off; off >>= 1) {
        if (tid < off) { sd[tid] += sd[tid+off]; sq[tid] += sq[tid+off]; }
        __syncthreads();
    }
    if (tid == 0) {
        const double mu  = sd[0] / (double)MROWS;
        const double var = sq[0] / (double)MROWS - mu*mu;
        const float rs = (float)rsqrt(var + 1e-5);
        const float sc = gam[c] * rs;
        g_sc2[c] = sc; g_sh2[c] = bet[c] - (float)mu*sc;
    }
}

// ======================= final pool =======================
__global__ void pool_kernel(float* __restrict__ out)
{
    const int i = blockIdx.x * 1024 + threadIdx.x;
    const int c = i & 127;
    out[NQ*3 + i] = fmaxf(fmaf(g_max[i], g_sc2[c], g_sh2[c]), 0.f);
}

// ======================= launch =======================
extern "C" void kernel_launch(void* const* d_in, const int* in_sizes, int n_in,
                              void* d_out, int out_size)
{
    const float* xyz = (const float*)d_in[0];
    const float* pts = (const float*)d_in[1];
    const float* w0  = (const float*)d_in[2];
    const float* gm0 = (const float*)d_in[4];
    const float* bt0 = (const float*)d_in[5];
    const float* w1  = (const float*)d_in[6];
    const float* gm1 = (const float*)d_in[8];
    const float* bt1 = (const float*)d_in[9];
    const float* w2  = (const float*)d_in[10];
    const float* gm2 = (const float*)d_in[12];
    const float* bt2 = (const float*)d_in[13];
    float* out = (float*)d_out;

    const int smFU = 67*130*4 + 67*128*4;   // 69144
    const int smM1 = 64*258*4 + 64*128*4;   // 98816
    const int smM2 = 64*130*4 + 64*256*4;   // 98816

    cudaFuncSetAttribute(fused_fps_fprep, cudaFuncAttributeMaxDynamicSharedMemorySize, smFU);
    cudaFuncSetAttribute(mm1_kernel, cudaFuncAttributeMaxDynamicSharedMemorySize, smM1);
    cudaFuncSetAttribute(mm2_kernel, cudaFuncAttributeMaxDynamicSharedMemorySize, smM2);

    prep_kernel<<<176, 256>>>(xyz, w1, w2);                 // idx 0
    fused_fps_fprep<<<264, 512, smFU>>>(pts, w0, out);      // idx 1
    stats0_kernel<<<2048, 256>>>(w0, gm0, bt0);             // idx 2 (qb + stats + finalize0)
    mm1_kernel<<<MROWS/256, 128, smM1>>>(w0, gm1, bt1);     // idx 3 (profiled)
    mm2_kernel<<<MROWS/128, 128, smM2>>>();                 // idx 4
    finalize_kernel<<<128, 256>>>(2, 2048, gm2, bt2);       // idx 5
    pool_kernel<<<(NQ*128)/1024, 1024>>>(out);              // idx 6
}

// round 15
// speedup vs baseline: 1.5005x; 1.0854x over previous
#include <cuda_runtime.h>

#define BATCH   8
#define NPTS    4096
#define NP      1024
#define NS      32
#define MROWS   262144
#define NQ      8192
#define NSRC    32768
#define RAD2    0.04f

typedef unsigned long long ull;
typedef unsigned int uint;

// ---------------- device scratch ----------------
__device__ float  g_F[NSRC*64];
__device__ float  g_Y1[(size_t)MROWS*64];
__device__ float  g_max[NQ*128];
__device__ float  g_nxyz[NQ*3];
__device__ int    g_gi[MROWS];
__device__ float2 g_p0[2048*64];
__device__ float2 g_p1[1024*64];
__device__ float2 g_p2[2048*128];
__device__ float  g_sc0[64], g_sh0[64];
__device__ float  g_sc1[64], g_sh1[64];
__device__ float  g_sc2[128], g_sh2[128];
__device__ float  g_sx[NSRC], g_sy[NSRC], g_sz[NSRC];
__device__ float  g_W1d[64*128];
__device__ float  g_W2d[64*256];
__device__ uint   g_ctr[3];

// ---------------- helpers ----------------
__device__ __forceinline__ void fma2(ull& d, ull a, ull b) {
    asm("fma.rn.f32x2 %0, %1, %2, %0;" : "+l"(d) : "l"(a), "l"(b));
}
__device__ __forceinline__ ull mul2(ull a, ull b) {
    ull d; asm("mul.rn.f32x2 %0, %1, %2;" : "=l"(d) : "l"(a), "l"(b)); return d;
}
__device__ __forceinline__ ull add2(ull a, ull b) {
    ull d; asm("add.rn.f32x2 %0, %1, %2;" : "=l"(d) : "l"(a), "l"(b)); return d;
}
__device__ __forceinline__ ull pack2(float lo, float hi) {
    ull d; asm("mov.b64 %0, {%1, %2};" : "=l"(d) : "f"(lo), "f"(hi)); return d;
}
__device__ __forceinline__ float2 u2f2(ull v) {
    float2 r; asm("mov.b64 {%0, %1}, %2;" : "=f"(r.x), "=f"(r.y) : "l"(v)); return r;
}
__device__ __forceinline__ uint rmax(uint v) {
    uint r; asm("redux.sync.max.u32 %0, %1, 0xffffffff;" : "=r"(r) : "r"(v)); return r;
}
__device__ __forceinline__ uint rmin(uint v) {
    uint r; asm("redux.sync.min.u32 %0, %1, 0xffffffff;" : "=r"(r) : "r"(v)); return r;
}

// ---------------- in-kernel BN finalize (deterministic last-block) ----------------
template<int C, int NB, int TPB>
__device__ void finalize_inblock(const float2* __restrict__ part,
                                 const float* __restrict__ gam,
                                 const float* __restrict__ bet,
                                 float* __restrict__ sc, float* __restrict__ sh,
                                 double* ws)   // 2*TPB doubles
{
    constexpr int PERC = TPB / C;
    double* fsd = ws;
    double* fsq = ws + TPB;
    const int tid = threadIdx.x;
    const int c = tid % C, rg = tid / C;
    double s = 0.0, q = 0.0;
    for (int i = rg; i < NB; i += PERC) {
        const float2 v = part[i*C + c];
        s += (double)v.x; q += (double)v.y;
    }
    fsd[tid] = s; fsq[tid] = q;
    __syncthreads();
    if (tid < C) {
        double ts = 0.0, tq = 0.0;
#pragma unroll
        for (int g = 0; g < PERC; ++g) { ts += fsd[g*C + tid]; tq += fsq[g*C + tid]; }
        const double mu  = ts / (double)MROWS;
        const double var = tq / (double)MROWS - mu*mu;
        const float rs = (float)rsqrt(var + 1e-5);
        const float scv = gam[tid] * rs;
        sc[tid] = scv;
        sh[tid] = bet[tid] - (float)mu * scv;
    }
}

// ======================= prep: SoA + weight permutation + counter reset =======================
__global__ __launch_bounds__(256) void prep_kernel(const float* __restrict__ xyz,
                                                   const float* __restrict__ w1,
                                                   const float* __restrict__ w2)
{
    const int tid = threadIdx.x, bx = blockIdx.x;
    if (bx < 128) {
        const int i = bx*256 + tid;
        const float x = xyz[i*3+0], y = xyz[i*3+1], z = xyz[i*3+2];
        g_sx[i] = x; g_sy[i] = y; g_sz[i] = z;
        if (bx == 0 && tid < 3) g_ctr[tid] = 0;
    } else if (bx < 144) {
        const int i = (bx-128)*256 + tid;          // < 4096
        const int n = i >> 6, k = i & 63;
        const float w = w1[i];
        const int p = 2*((n & 7)*8 + (n >> 3));
        g_W1d[k*128 + p] = w; g_W1d[k*128 + p + 1] = w;
    } else {
        const int i = (bx-144)*256 + tid;          // < 8192
        const int n = i >> 6, k = i & 63;
        const float w = w2[i];
        const int p = 2*((n & 7)*16 + (n >> 3));
        g_W2d[k*256 + p] = w; g_W2d[k*256 + p + 1] = w;
    }
}

// ======================= 1a) FPS (register-resident, f32x2 update) =======================
__device__ void fps_block(float* __restrict__ out, float* sm, int b)
{
    float* xs = sm;
    float* ys = sm + NPTS;
    float* zs = sm + 2*NPTS;
    uint* wkd = (uint*)(sm + 3*NPTS);   // [2][16]
    uint* wki = wkd + 32;               // [2][16]

    const int tid  = threadIdx.x;       // 512
    const int lane = tid & 31;
    const int warp = tid >> 5;
    const int off = b * NPTS;

    for (int i = tid; i < NPTS; i += 512) {
        xs[i] = g_sx[off + i]; ys[i] = g_sy[off + i]; zs[i] = g_sz[off + i];
    }
    __syncthreads();

    ull nx2[4], ny2[4], nz2[4];
    float dl[8];
#pragma unroll
    for (int jj = 0; jj < 4; ++jj) {
        const int p0 = tid + (2*jj)*512, p1 = tid + (2*jj+1)*512;
        nx2[jj] = pack2(-xs[p0], -xs[p1]);
        ny2[jj] = pack2(-ys[p0], -ys[p1]);
        nz2[jj] = pack2(-zs[p0], -zs[p1]);
    }
#pragma unroll
    for (int j = 0; j < 8; ++j) dl[j] = 1e10f;

    int far = 0, buf = 0;
    for (int it = 0; it < NP; ++it) {
        const float cx = xs[far], cy = ys[far], cz = zs[far];
        const ull cx2 = pack2(cx, cx), cy2 = pack2(cy, cy), cz2 = pack2(cz, cz);
#pragma unroll
        for (int jj = 0; jj < 4; ++jj) {
            const ull dx2 = add2(cx2, nx2[jj]);   // cx + (-x): bit-identical squares
            const ull dy2 = add2(cy2, ny2[jj]);
            const ull dz2 = add2(cz2, nz2[jj]);
            ull dd2 = mul2(dx2, dx2);
            fma2(dd2, dy2, dy2);
            fma2(dd2, dz2, dz2);
            const float2 f = u2f2(dd2);
            dl[2*jj]   = fminf(dl[2*jj],   f.x);
            dl[2*jj+1] = fminf(dl[2*jj+1], f.y);
        }
        if (tid == 0) {
            const int o = (b*NP + it)*3;
            g_nxyz[o+0] = cx; g_nxyz[o+1] = cy; g_nxyz[o+2] = cz;
            out[o+0] = cx;    out[o+1] = cy;    out[o+2] = cz;
        }
        const float t01 = fmaxf(dl[0], dl[1]), t23 = fmaxf(dl[2], dl[3]);
        const float t45 = fmaxf(dl[4], dl[5]), t67 = fmaxf(dl[6], dl[7]);
        const float tmax = fmaxf(fmaxf(t01, t23), fmaxf(t45, t67));
        int idx = tid + 7*512;
#pragma unroll
        for (int j = 6; j >= 0; --j) idx = (dl[j] == tmax) ? (tid + j*512) : idx;

        const uint tb   = __float_as_uint(tmax);
        const uint wmax = rmax(tb);
        const uint wi   = rmin((tb == wmax) ? (uint)idx : 0x7fffffffu);
        if (lane == 0) { wkd[buf*16 + warp] = wmax; wki[buf*16 + warp] = wi; }
        __syncthreads();
        const uint dd2v = (lane < 16) ? wkd[buf*16 + lane] : 0u;
        const uint ii2v = (lane < 16) ? wki[buf*16 + lane] : 0x7fffffffu;
        const uint bmax = rmax(dd2v);
        far = (int)rmin((dd2v == bmax) ? ii2v : 0x7fffffffu);
        buf ^= 1;
    }
}

// ======================= 1b) fprep: F = concat(xyz, pts) @ W0^T =======================
__device__ void fprep_block(const float* __restrict__ pts,
                            const float* __restrict__ W, float* smf, int blk)
{
    float* XsT = smf;               // [67][130]
    float* WtD = smf + 67*130;      // [67][128]
    const int tid = threadIdx.x;    // 512

    for (int i = tid; i < 67*64; i += 512) {
        const int n = i / 67, k = i - n*67;
        const float w = W[i];
        const int p = 2*((n & 3)*16 + (n >> 2));
        WtD[k*128 + p] = w; WtD[k*128 + p + 1] = w;
    }
    for (int i = tid; i < 128*67; i += 512) {
        const int lr = i / 67, c = i - lr*67;
        const int row = blk*128 + lr;
        float v;
        if (c >= 3)     v = pts[(size_t)row*64 + (c-3)];
        else if (c==0)  v = g_sx[row];
        else if (c==1)  v = g_sy[row];
        else            v = g_sz[row];
        XsT[c*130 + lr] = v;
    }
    __syncthreads();

    const int tx = tid & 15;
    const int ty = tid >> 4;
    ull acc[2][4] = {};
#pragma unroll 4
    for (int k = 0; k < 67; ++k) {
        ull a[2], bv[4];
#pragma unroll
        for (int i2 = 0; i2 < 2; ++i2) a[i2] = *(const ull*)&XsT[k*130 + ty*4 + 2*i2];
#pragma unroll
        for (int j = 0; j < 4; ++j)    bv[j] = *(const ull*)&WtD[k*128 + 2*(j*16 + tx)];
#pragma unroll
        for (int i2 = 0; i2 < 2; ++i2)
#pragma unroll
            for (int j = 0; j < 4; ++j) fma2(acc[i2][j], a[i2], bv[j]);
    }
    const int rbase = blk*128 + ty*4;
#pragma unroll
    for (int i2 = 0; i2 < 2; ++i2) {
        float2 t[4];
#pragma unroll
        for (int j = 0; j < 4; ++j) t[j] = u2f2(acc[i2][j]);
        const int r = rbase + 2*i2;
        *(float4*)&g_F[(size_t)r*64 + tx*4]     = make_float4(t[0].x, t[1].x, t[2].x, t[3].x);
        *(float4*)&g_F[(size_t)(r+1)*64 + tx*4] = make_float4(t[0].y, t[1].y, t[2].y, t[3].y);
    }
}

__global__ __launch_bounds__(512) void fused_fps_fprep(const float* __restrict__ pts,
                                                       const float* __restrict__ w0,
                                                       float* __restrict__ out)
{
    extern __shared__ float sm[];
    if (blockIdx.x < 8) fps_block(out, sm, blockIdx.x);
    else                fprep_block(pts, w0, sm, blockIdx.x - 8);
}

// ======================= 2) stats0: local ball-query + layer-0 stats + finalize0 =======================
__global__ __launch_bounds__(256) void stats0_kernel(const float* __restrict__ w0,
                                                     const float* __restrict__ gam,
                                                     const float* __restrict__ bet)
{
    __shared__ float sw[192];
    __shared__ float sd[256], sq[256];
    __shared__ int   sIdxS[128];
    __shared__ double fws[512];
    __shared__ bool  isLast;
    const int tid = threadIdx.x, blk = blockIdx.x;
    const int lane = tid & 31, warp = tid >> 5;
    for (int i = tid; i < 192; i += 256) sw[i] = w0[(i/3)*67 + (i%3)];

    // ---- ball query for this block's 4 queries (warps 0-3) ----
    if (warp < 4) {
        const int q = blk*4 + warp;
        const int b = q >> 10;
        const int off = b * NPTS;
        const float cx = g_nxyz[q*3+0], cy = g_nxyz[q*3+1], cz = g_nxyz[q*3+2];
        int* g = g_gi + q*NS;
        int cnt = 0, first = -1;
        for (int r = 0; r < NPTS/32; ++r) {
            const int n = r*32 + lane;
            const float dx = g_sx[off+n]-cx, dy = g_sy[off+n]-cy, dz = g_sz[off+n]-cz;
            const float d2 = dx*dx + dy*dy + dz*dz;
            const bool in = (d2 <= RAD2);
            const unsigned m = __ballot_sync(0xFFFFFFFFu, in);
            if (first < 0 && m) first = r*32 + __ffs(m) - 1;
            const int pos = cnt + __popc(m & ((1u << lane) - 1u));
            if (in && pos < NS) { g[pos] = n; sIdxS[warp*32 + pos] = n; }
            cnt += __popc(m);
            if (cnt >= NS) break;
        }
        for (int i = cnt + lane; i < NS; i += 32) { g[i] = first; sIdxS[warp*32 + i] = first; }
    }
    __syncthreads();

    // ---- stats over this block's 128 rows ----
    const int c = tid & 63, rg = tid >> 6;
    float s = 0.f, q = 0.f;
#pragma unroll 4
    for (int r = rg; r < 128; r += 4) {
        const int row = blk*128 + r;
        const int b = row >> 15;
        const int qg = row >> 5;
        const int idx = sIdxS[r];
        const float Cc = g_nxyz[qg*3+0]*sw[c*3+0]
                       + g_nxyz[qg*3+1]*sw[c*3+1]
                       + g_nxyz[qg*3+2]*sw[c*3+2];
        const float v = g_F[(((size_t)b << 12) + idx)*64 + c] - Cc;
        s += v; q = fmaf(v, v, q);
    }
    sd[tid] = s; sq[tid] = q;
    __syncthreads();
    if (tid < 64) {
        g_p0[blk*64 + tid] = make_float2(sd[tid] + sd[64+tid] + sd[128+tid] + sd[192+tid],
                                         sq[tid] + sq[64+tid] + sq[128+tid] + sq[192+tid]);
    }
    __threadfence();
    if (tid == 0) isLast = (atomicAdd(&g_ctr[0], 1u) == 2047u);
    __syncthreads();
    if (isLast) {
        __threadfence();
        finalize_inblock<64, 2048, 256>(g_p0, gam, bet, g_sc0, g_sh0, fws);
    }
}

// ======================= 3) mm1: 256 threads, 8x8 thread tile (+finalize1) =======================
__global__ __launch_bounds__(256, 2) void mm1_kernel(const float* __restrict__ w0,
                                                     const float* __restrict__ gam,
                                                     const float* __restrict__ bet)
{
    extern __shared__ float smf[];
    float* XsT  = smf;              // [64][258]
    float* WtD  = smf + 64*258;     // [64][128] = 8192 floats
    float* ssum = WtD;              // alias post-GEMM [32][64]
    float* ssq  = WtD + 32*64;      // [32][64]
    double* fws = (double*)(WtD + 64*64);   // 512 doubles = floats [4096,5120)
    __shared__ float sW0x[192];
    __shared__ float sCtr[24];
    __shared__ int   sIdx[256];
    __shared__ bool  isLast;

    const int tid = threadIdx.x, blk = blockIdx.x;

    for (int i = tid; i < 64*128/4; i += 256)
        ((float4*)WtD)[i] = ((const float4*)g_W1d)[i];
    for (int i = tid; i < 192; i += 256) sW0x[i] = w0[(i/3)*67 + (i%3)];
    if (tid < 24) sCtr[tid] = g_nxyz[(blk*8 + tid/3)*3 + (tid%3)];
    if (tid < 256) sIdx[tid] = g_gi[blk*256 + tid];
    __syncthreads();

    // gather + bn0 + relu, float4 loads of g_F
    const int bb = blk >> 7;
    for (int i = tid; i < 256*16; i += 256) {
        const int lr = i >> 4, f4 = i & 15;
        const int g = lr >> 5;
        const int idx = sIdx[lr];
        const float4 fv = *(const float4*)&g_F[(((size_t)bb << 12) + idx)*64 + f4*4];
        const float vv[4] = {fv.x, fv.y, fv.z, fv.w};
#pragma unroll
        for (int u = 0; u < 4; ++u) {
            const int c = f4*4 + u;
            const float Cc = sCtr[g*3+0]*sW0x[c*3+0]
                           + sCtr[g*3+1]*sW0x[c*3+1]
                           + sCtr[g*3+2]*sW0x[c*3+2];
            float v = vv[u] - Cc;
            v = fmaxf(fmaf(v, g_sc0[c], g_sh0[c]), 0.f);
            XsT[c*258 + lr] = v;
        }
    }
    __syncthreads();

    const int tx = tid & 7;     // 8 colgroups x 8 cols
    const int ty = tid >> 3;    // 32 rowgroups x 8 rows
    ull acc[4][8] = {};
#pragma unroll 1
    for (int k = 0; k < 64; ++k) {
        ull a[4], bv[8];
#pragma unroll
        for (int i2 = 0; i2 < 4; ++i2) a[i2] = *(const ull*)&XsT[k*258 + ty*8 + 2*i2];
#pragma unroll
        for (int j = 0; j < 8; ++j)    bv[j] = *(const ull*)&WtD[k*128 + 2*(j*8 + tx)];
#pragma unroll
        for (int i2 = 0; i2 < 4; ++i2)
#pragma unroll
            for (int j = 0; j < 8; ++j) fma2(acc[i2][j], a[i2], bv[j]);
    }

    float ls[8], lq[8];
#pragma unroll
    for (int j = 0; j < 8; ++j) {
        float s = 0.f, q = 0.f;
#pragma unroll
        for (int i2 = 0; i2 < 4; ++i2) {
            const float2 v = u2f2(acc[i2][j]);
            s += v.x; s += v.y;
            q = fmaf(v.x, v.x, q); q = fmaf(v.y, v.y, q);
        }
        ls[j] = s; lq[j] = q;
    }
    const int rbase = blk*256 + ty*8;
#pragma unroll
    for (int i2 = 0; i2 < 4; ++i2) {
        float2 t[8];
#pragma unroll
        for (int j = 0; j < 8; ++j) t[j] = u2f2(acc[i2][j]);   // col = 8*tx + j
        const int r = rbase + 2*i2;
        float* y0 = &g_Y1[(size_t)r*64 + tx*8];
        ((float4*)y0)[0] = make_float4(t[0].x, t[1].x, t[2].x, t[3].x);
        ((float4*)y0)[1] = make_float4(t[4].x, t[5].x, t[6].x, t[7].x);
        float* y1 = &g_Y1[(size_t)(r+1)*64 + tx*8];
        ((float4*)y1)[0] = make_float4(t[0].y, t[1].y, t[2].y, t[3].y);
        ((float4*)y1)[1] = make_float4(t[4].y, t[5].y, t[6].y, t[7].y);
    }
    __syncthreads();   // WtD done -> alias
#pragma unroll
    for (int j = 0; j < 8; ++j) {
        ssum[ty*64 + tx*8 + j] = ls[j];
        ssq [ty*64 + tx*8 + j] = lq[j];
    }
    __syncthreads();
    if (tid < 64) {
        float s = 0.f, q = 0.f;
#pragma unroll
        for (int t = 0; t < 32; ++t) { s += ssum[t*64 + tid]; q += ssq[t*64 + tid]; }
        g_p1[blk*64 + tid] = make_float2(s, q);
    }
    __threadfence();
    if (tid == 0) isLast = (atomicAdd(&g_ctr[1], 1u) == 1023u);
    __syncthreads();
    if (isLast) {
        __threadfence();
        finalize_inblock<64, 1024, 256>(g_p1, gam, bet, g_sc1, g_sh1, fws);
    }
}

// ======================= 4) mm2: 256 threads, 8x8 thread tile (+stats +max-pool) =======================
__global__ __launch_bounds__(256, 2) void mm2_kernel()
{
    extern __shared__ float smf[];
    float* XsT  = smf;              // [64][130]
    float* WtD  = smf + 64*130;     // [64][256] = 16384 floats
    float* ssum = WtD;              // alias [16][128]
    float* ssq  = WtD + 16*128;
    float* smax = WtD + 32*128;

    const int tid = threadIdx.x, blk = blockIdx.x;

    for (int i = tid; i < 64*256/4; i += 256)
        ((float4*)WtD)[i] = ((const float4*)g_W2d)[i];
    // bn1 + relu, float4 loads of g_Y1
    for (int i = tid; i < 128*16; i += 256) {
        const int lr = i >> 4, f4 = i & 15;
        const float4 fv = *(const float4*)&g_Y1[((size_t)blk*128 + lr)*64 + f4*4];
        const float vv[4] = {fv.x, fv.y, fv.z, fv.w};
#pragma unroll
        for (int u = 0; u < 4; ++u) {
            const int c = f4*4 + u;
            float v = fmaxf(fmaf(vv[u], g_sc1[c], g_sh1[c]), 0.f);
            XsT[c*130 + lr] = v;
        }
    }
    __syncthreads();

    const int tx = tid & 15;    // 16 colgroups x 8 cols
    const int ty = tid >> 4;    // 16 rowgroups x 8 rows
    ull acc[4][8] = {};
#pragma unroll 1
    for (int k = 0; k < 64; ++k) {
        ull a[4], bv[8];
#pragma unroll
        for (int i2 = 0; i2 < 4; ++i2) a[i2] = *(const ull*)&XsT[k*130 + ty*8 + 2*i2];
#pragma unroll
        for (int j = 0; j < 8; ++j)    bv[j] = *(const ull*)&WtD[k*256 + 2*(j*16 + tx)];
#pragma unroll
        for (int i2 = 0; i2 < 4; ++i2)
#pragma unroll
            for (int j = 0; j < 8; ++j) fma2(acc[i2][j], a[i2], bv[j]);
    }

    // cols = 8*tx + j; rows ty*8..ty*8+7 all inside query group g = ty>>2
    float ls[8], lq[8], lm[8];
#pragma unroll
    for (int j = 0; j < 8; ++j) {
        float s = 0.f, q = 0.f, m = -3.4e38f;
#pragma unroll
        for (int i2 = 0; i2 < 4; ++i2) {
            const float2 v = u2f2(acc[i2][j]);
            s += v.x; s += v.y;
            q = fmaf(v.x, v.x, q); q = fmaf(v.y, v.y, q);
            m = fmaxf(m, fmaxf(v.x, v.y));
        }
        ls[j] = s; lq[j] = q; lm[j] = m;
    }
    __syncthreads();   // WtD done -> alias
#pragma unroll
    for (int j = 0; j < 8; ++j) {
        const int c = tx*8 + j;
        ssum[ty*128 + c] = ls[j];
        ssq [ty*128 + c] = lq[j];
        smax[ty*128 + c] = lm[j];
    }
    __syncthreads();
    if (tid < 128) {
        float s = 0.f, q = 0.f;
#pragma unroll
        for (int t = 0; t < 16; ++t) { s += ssum[t*128 + tid]; q += ssq[t*128 + tid]; }
        g_p2[blk*128 + tid] = make_float2(s, q);
    }
    for (int w = tid; w < 512; w += 256) {
        const int g = w >> 7, c = w & 127;
        float m = smax[(4*g+0)*128 + c];
        m = fmaxf(m, smax[(4*g+1)*128 + c]);
        m = fmaxf(m, smax[(4*g+2)*128 + c]);
        m = fmaxf(m, smax[(4*g+3)*128 + c]);
        g_max[(blk*4 + g)*128 + c] = m;
    }
}

// ======================= finalize BN (layer 2) =======================
__global__ void finalize_kernel(const float* __restrict__ gam,
                                const float* __restrict__ bet)
{
    const int c = blockIdx.x;     // 128
    const int tid = threadIdx.x;  // 256
    __shared__ double sd[256], sq[256];
    double s = 0.0, q = 0.0;
    for (int i = tid; i < 2048; i += 256) {
        const float2 v = g_p2[i*128 + c];
        s += (double)v.x; q += (double)v.y;
    }
    sd[tid] = s; sq[tid] = q;
    __syncthreads();
    for (int off = 128; off; off >>= 1) {
        if (tid < off) { sd[tid] += sd[tid+off]; sq[tid] += sq[tid+off]; }
        __syncthreads();
    }
    if (tid == 0) {
        const double mu  = sd[0] / (double)MROWS;
        const double var = sq[0] / (double)MROWS - mu*mu;
        const float rs = (float)rsqrt(var + 1e-5);
        const float sc = gam[c] * rs;
        g_sc2[c] = sc; g_sh2[c] = bet[c] - (float)mu*sc;
    }
}

// ======================= final pool =======================
__global__ void pool_kernel(float* __restrict__ out)
{
    const int i = blockIdx.x * 1024 + threadIdx.x;
    const int c = i & 127;
    out[NQ*3 + i] = fmaxf(fmaf(g_max[i], g_sc2[c], g_sh2[c]), 0.f);
}

// ======================= launch =======================
extern "C" void kernel_launch(void* const* d_in, const int* in_sizes, int n_in,
                              void* d_out, int out_size)
{
    const float* xyz = (const float*)d_in[0];
    const float* pts = (const float*)d_in[1];
    const float* w0  = (const float*)d_in[2];
    const float* gm0 = (const float*)d_in[4];
    const float* bt0 = (const float*)d_in[5];
    const float* w1  = (const float*)d_in[6];
    const float* gm1 = (const float*)d_in[8];
    const float* bt1 = (const float*)d_in[9];
    const float* w2  = (const float*)d_in[10];
    const float* gm2 = (const float*)d_in[12];
    const float* bt2 = (const float*)d_in[13];
    float* out = (float*)d_out;

    const int smFU = 67*130*4 + 67*128*4;   // 69144
    const int smM1 = 64*258*4 + 64*128*4;   // 98816
    const int smM2 = 64*130*4 + 64*256*4;   // 98816

    cudaFuncSetAttribute(fused_fps_fprep, cudaFuncAttributeMaxDynamicSharedMemorySize, smFU);
    cudaFuncSetAttribute(mm1_kernel, cudaFuncAttributeMaxDynamicSharedMemorySize, smM1);
    cudaFuncSetAttribute(mm2_kernel, cudaFuncAttributeMaxDynamicSharedMemorySize, smM2);

    prep_kernel<<<176, 256>>>(xyz, w1, w2);                 // idx 0
    fused_fps_fprep<<<264, 512, smFU>>>(pts, w0, out);      // idx 1
    stats0_kernel<<<2048, 256>>>(w0, gm0, bt0);             // idx 2
    mm1_kernel<<<MROWS/256, 256, smM1>>>(w0, gm1, bt1);     // idx 3 (profiled)
    mm2_kernel<<<MROWS/128, 256, smM2>>>();                 // idx 4
    finalize_kernel<<<128, 256>>>(gm2, bt2);                // idx 5
    pool_kernel<<<(NQ*128)/1024, 1024>>>(out);              // idx 6
}